// round 14
// baseline (speedup 1.0000x reference)
#include <cuda_runtime.h>
#include <math.h>

#define NPROP 1000
#define NPAD  1024          /* padded row length for transposed matrices */
#define NCLS  91
#define TOPK  100
#define NMAX  1024
#define MCAP  256           /* fast parallel-NMS path capacity */
#define BLK   256
#define GRID  (NCLS - 1)
#define NITER 4             /* ceil(NPROP / BLK) */
#define ROWS_PB 16          /* rows per prep block */
#define PITCH 17            /* smem row pitch (conflict-free) */
#define SCORE_TH 0.05f
#define NMS_TH   0.5f
#define MIN_SIZE 1.0f
#define BBOX_CLIP 4.1351665567423f   /* log(1000/16) */

// transposed per-class matrices, written by A (coalesced via smem staging)
__device__ float  g_score[NCLS * NPAD];   // score, or -1 if score/size filtered
__device__ float4 g_box[NCLS * NPAD];     // decoded + clipped box

__device__ __forceinline__ float read_dim(const void* p) {
    int iv = *(const int*)p;
    if (iv >= 1 && iv <= 100000) return (float)iv;        // int32 / int64 low word
    float fv = __int_as_float(iv);
    if (fv >= 1.0f && fv <= 100000.0f) return fv;          // float32
    return (float)iv;
}

// ---- kernel A: 16 rows/block, warp-per-row compute, staged coalesced writes ----
__global__ __launch_bounds__(BLK, 1)
void prep_kernel(const float* __restrict__ class_logit,   // [N, C]
                 const float* __restrict__ box_reg,       // [N, C*4]
                 const float* __restrict__ proposal,      // [N, 4]
                 const void*  __restrict__ p_img_h,
                 const void*  __restrict__ p_img_w)
{
    __shared__ float s_sc[NCLS * PITCH];
    __shared__ float s_x1[NCLS * PITCH];
    __shared__ float s_y1[NCLS * PITCH];
    __shared__ float s_x2[NCLS * PITCH];
    __shared__ float s_y2[NCLS * PITCH];

    const int tid  = threadIdx.x;
    const int wid  = tid >> 5;
    const int lane = tid & 31;
    const int row0 = blockIdx.x * ROWS_PB;

    const float img_h = read_dim(p_img_h);
    const float img_w = read_dim(p_img_w);

    // ---- compute: warp w handles local rows w and w+8 ----
    #pragma unroll
    for (int k = 0; k < 2; ++k) {
        const int r   = wid + 8 * k;           // local row 0..15
        const int row = row0 + r;
        if (row < NPROP) {
            const float* lg = class_logit + row * NCLS;
            const float l0 = lg[lane];
            const float l1 = lg[lane + 32];
            const bool  has2 = (lane + 64 < NCLS);
            const float l2 = has2 ? lg[lane + 64] : -3.4e38f;

            float m = fmaxf(l0, fmaxf(l1, l2));
            #pragma unroll
            for (int o = 16; o; o >>= 1) m = fmaxf(m, __shfl_xor_sync(0xffffffffu, m, o));

            const float e0 = expf(l0 - m);
            const float e1 = expf(l1 - m);
            const float e2 = has2 ? expf(l2 - m) : 0.0f;
            float s = e0 + e1 + e2;
            #pragma unroll
            for (int o = 16; o; o >>= 1) s += __shfl_xor_sync(0xffffffffu, s, o);
            const float rinv = 1.0f / s;

            const float4 pr = ((const float4*)proposal)[row];
            const float w  = pr.z - pr.x;
            const float h  = pr.w - pr.y;
            const float cx = pr.x + 0.5f * w;
            const float cy = pr.y + 0.5f * h;

            const float4* breg = (const float4*)(box_reg + row * (NCLS * 4));

            #pragma unroll
            for (int q = 0; q < 3; ++q) {
                const int c = lane + 32 * q;
                if (c >= NCLS) break;
                const float ec = (q == 0) ? e0 : (q == 1) ? e1 : e2;
                const float score = ec * rinv;

                float outsc = -1.0f;
                float bx1 = 0.f, by1 = 0.f, bx2 = 0.f, by2 = 0.f;
                if (c >= 1 && score >= SCORE_TH) {
                    const float4 d = breg[c];    // coalesced across lanes
                    const float dx = d.x * 0.1f;
                    const float dy = d.y * 0.1f;
                    const float dw = fminf(d.z * 0.2f, BBOX_CLIP);
                    const float dh = fminf(d.w * 0.2f, BBOX_CLIP);

                    const float pcx = dx * w + cx;
                    const float pcy = dy * h + cy;
                    const float pw  = expf(dw) * w;
                    const float ph  = expf(dh) * h;

                    bx1 = fminf(fmaxf(pcx - 0.5f * pw, 0.0f), img_w);
                    by1 = fminf(fmaxf(pcy - 0.5f * ph, 0.0f), img_h);
                    bx2 = fminf(fmaxf(pcx + 0.5f * pw, 0.0f), img_w);
                    by2 = fminf(fmaxf(pcy + 0.5f * ph, 0.0f), img_h);

                    if (bx2 - bx1 >= MIN_SIZE && by2 - by1 >= MIN_SIZE) outsc = score;
                }
                const int si = c * PITCH + r;    // stride-17: conflict-free
                s_sc[si] = outsc;
                s_x1[si] = bx1; s_y1[si] = by1;
                s_x2[si] = bx2; s_y2[si] = by2;
            }
        } else {
            // pad rows: mark filtered so write-out stays uniform
            #pragma unroll
            for (int q = 0; q < 3; ++q) {
                const int c = lane + 32 * q;
                if (c >= NCLS) break;
                s_sc[c * PITCH + r] = -1.0f;
            }
        }
    }
    __syncthreads();

    // ---- write-out: consecutive threads -> consecutive rows of one class ----
    // scores: 64B contiguous chunks per class; boxes: 256B chunks per class.
    for (int idx = tid; idx < NCLS * ROWS_PB; idx += BLK) {
        const int c = idx >> 4;          // idx / 16
        const int r = idx & 15;
        const int row = row0 + r;
        if (row < NPROP) {
            const int si = c * PITCH + r;
            const float sc = s_sc[si];
            g_score[c * NPAD + row] = sc;
            g_box[c * NPAD + row] = make_float4(s_x1[si], s_y1[si], s_x2[si], s_y2[si]);
        }
    }

    __threadfence();
#if __CUDA_ARCH__ >= 900
    cudaTriggerProgrammaticLaunchCompletion();
#endif
}

// ---- kernel B: per-class compact + rank sort + parallel NMS + top-K ----
__global__ __launch_bounds__(BLK, 1)
void roi_main_kernel(float* __restrict__ out, int out_size)
{
    const int c    = blockIdx.x + 1;     // foreground class 1..90
    const int tid  = threadIdx.x;
    const int wid  = tid >> 5;
    const int lane = tid & 31;

    __shared__ unsigned long long s_key[NMAX];
    __shared__ float4 s_cbox[NMAX];                 // boxes (compact order)
    __shared__ int    s_perm[NMAX];                 // sorted pos -> compact slot
    __shared__ float4 s_sb[MCAP];                   // boxes in sorted order
    __shared__ unsigned long long s_maskT[MCAP * 4];// transposed suppression matrix
    __shared__ unsigned int s_half[8];              // keep-set, 8x32 bits
    __shared__ unsigned char s_keep[NMAX];          // fallback path only
    __shared__ int    s_list[TOPK];
    __shared__ int    s_mcnt, s_cnt;

    if (tid == 0) s_mcnt = 0;
    __syncthreads();

#if __CUDA_ARCH__ >= 900
    cudaGridDependencySynchronize();    // wait for kernel A
#endif

    // ---- phase 1: two coalesced batched loads, then compact ----
    float  sc4[NITER];
    float4 bx4[NITER];
    #pragma unroll
    for (int k = 0; k < NITER; ++k) {
        const int p = tid + k * BLK;
        sc4[k] = (p < NPROP) ? __ldcg(&g_score[c * NPAD + p]) : -1.0f;
    }
    #pragma unroll
    for (int k = 0; k < NITER; ++k) {
        const int p = tid + k * BLK;
        bx4[k] = (p < NPROP && sc4[k] >= 0.0f) ? __ldcg(&g_box[c * NPAD + p])
                                               : make_float4(0.f, 0.f, 0.f, 0.f);
    }
    #pragma unroll
    for (int k = 0; k < NITER; ++k) {
        const int p = tid + k * BLK;
        if (p < NPROP && sc4[k] >= 0.0f) {
            const int slot = atomicAdd(&s_mcnt, 1);
            s_cbox[slot] = bx4[k];
            s_key[slot]  = ((unsigned long long)__float_as_uint(sc4[k]) << 32)
                         | (unsigned int)(NPROP - p);
        }
    }
    __syncthreads();

    const int M = s_mcnt;      // all entries valid (filtering done in A)

    // ---- rank sort (keys unique -> ranks are a bijection) ----
    for (int i = tid; i < M; i += BLK) {
        const unsigned long long ki = s_key[i];
        int r = 0;
        for (int j = 0; j < M; ++j) r += (s_key[j] > ki);
        s_perm[r] = i;
    }
    __syncthreads();

    const bool fast = (M <= MCAP);

    if (fast) {
        // ---- materialize sorted boxes; init keep-set ----
        for (int i = tid; i < M; i += BLK) s_sb[i] = s_cbox[s_perm[i]];
        if (tid < 8) {
            const int lo = tid * 32;
            s_half[tid] = (M >= lo + 32) ? 0xffffffffu
                        : (M <= lo) ? 0u
                        : ((1u << (M - lo)) - 1u);
        }
        __syncthreads();

        // ---- transposed suppression matrix: bit j of row i iff j<i & IoU>th ----
        for (int t = tid; t < M * 4; t += BLK) {
            const int i = t >> 2;
            const int w = t & 3;
            unsigned long long bits = 0ULL;
            const int jbase = w << 6;
            const int jend  = min(jbase + 64, i);     // j < i only
            if (jend > jbase) {
                const float4 a = s_sb[i];
                const float area_a = (a.z - a.x) * (a.w - a.y);
                for (int j = jbase; j < jend; ++j) {
                    const float4 b = s_sb[j];
                    const float area_b = (b.z - b.x) * (b.w - b.y);
                    const float iw = fmaxf(fminf(a.z, b.z) - fmaxf(a.x, b.x), 0.0f);
                    const float ih = fmaxf(fminf(a.w, b.w) - fmaxf(a.y, b.y), 0.0f);
                    const float inter = iw * ih;
                    const float uni   = fmaxf(area_a + area_b - inter, 1e-6f);
                    if (inter > NMS_TH * uni) bits |= 1ULL << (j - jbase);
                }
            }
            s_maskT[t] = bits;
        }
        __syncthreads();

        // ---- parallel Jacobi fixpoint == greedy NMS (unique fixpoint) ----
        const int i = tid;
        int guard = 0;
        for (;;) {
            bool nk = false, ch = false;
            if (i < M) {
                const unsigned long long k0 =
                    (unsigned long long)s_half[0] | ((unsigned long long)s_half[1] << 32);
                const unsigned long long k1 =
                    (unsigned long long)s_half[2] | ((unsigned long long)s_half[3] << 32);
                const unsigned long long k2 =
                    (unsigned long long)s_half[4] | ((unsigned long long)s_half[5] << 32);
                const unsigned long long k3 =
                    (unsigned long long)s_half[6] | ((unsigned long long)s_half[7] << 32);
                const unsigned long long sup =
                      (s_maskT[i * 4 + 0] & k0) | (s_maskT[i * 4 + 1] & k1)
                    | (s_maskT[i * 4 + 2] & k2) | (s_maskT[i * 4 + 3] & k3);
                nk = (sup == 0ULL);
                const bool cur = (s_half[i >> 5] >> (i & 31)) & 1u;
                ch = (nk != cur);
            }
            const unsigned int bal = __ballot_sync(0xffffffffu, nk);
            __syncthreads();                      // all reads done before rewrite
            if (lane == 0) s_half[wid] = bal;     // 8 warps cover 8 words exactly
            if (!__syncthreads_or((int)ch)) break;
            if (++guard > MCAP) break;            // safety bound (never hit)
        }

        // ---- top-K compaction from 8 keep words (register-only ffs loop) ----
        if (tid == 0) {
            int cnt = 0;
            #pragma unroll
            for (int hw = 0; hw < 8; ++hw) {
                unsigned int a = s_half[hw];
                while (a && cnt < TOPK) {
                    const int b = __ffs(a) - 1;
                    s_list[cnt++] = hw * 32 + b;
                    a &= a - 1;
                }
            }
            s_cnt = cnt;
        }
        __syncthreads();
    } else {
        // ---- fallback: barrier-per-round NMS over sorted order (any M) ----
        for (int i = tid; i < M; i += BLK) s_keep[i] = 1;
        __syncthreads();
        for (int i = 0; i < M - 1; ++i) {
            if (!s_keep[i]) continue;
            const float4 a = s_cbox[s_perm[i]];
            const float area_a = (a.z - a.x) * (a.w - a.y);
            for (int j = i + 1 + tid; j < M; j += BLK) {
                if (!s_keep[j]) continue;
                const float4 b = s_cbox[s_perm[j]];
                const float area_b = (b.z - b.x) * (b.w - b.y);
                const float iw = fmaxf(fminf(a.z, b.z) - fmaxf(a.x, b.x), 0.0f);
                const float ih = fmaxf(fminf(a.w, b.w) - fmaxf(a.y, b.y), 0.0f);
                const float inter = iw * ih;
                const float uni   = fmaxf(area_a + area_b - inter, 1e-6f);
                if (inter > NMS_TH * uni) s_keep[j] = 0;
            }
            __syncthreads();
        }
        if (tid == 0) {
            int cnt = 0;
            for (int i = 0; i < M && cnt < TOPK; ++i)
                if (s_keep[i]) s_list[cnt++] = i;
            s_cnt = cnt;
        }
        __syncthreads();
    }

    // ---- write output: dets [9000,5] then labels [9000] (as float) ----
    if (tid < TOPK) {
        const int r = (c - 1) * TOPK + tid;
        float b0 = 0.f, b1 = 0.f, b2 = 0.f, b3 = 0.f, sc = 0.f, lab = 0.f;
        if (tid < s_cnt) {
            const int pos  = s_list[tid];
            const int slot = s_perm[pos];
            const float4 b = fast ? s_sb[pos] : s_cbox[slot];
            b0 = b.x; b1 = b.y; b2 = b.z; b3 = b.w;
            sc = __uint_as_float((unsigned int)(s_key[slot] >> 32));
            lab = (float)c;
        }
        out[r * 5 + 0] = b0;
        out[r * 5 + 1] = b1;
        out[r * 5 + 2] = b2;
        out[r * 5 + 3] = b3;
        out[r * 5 + 4] = sc;
        const int dets_elems = (NCLS - 1) * TOPK * 5;        // 45000
        if (out_size >= dets_elems + (NCLS - 1) * TOPK)
            out[dets_elems + r] = lab;
    }
}

extern "C" void kernel_launch(void* const* d_in, const int* in_sizes, int n_in,
                              void* d_out, int out_size)
{
    const float* class_logit = (const float*)d_in[0];
    const float* box_reg     = (const float*)d_in[1];
    const float* proposal    = (const float*)d_in[2];
    const void*  img_h       = d_in[3];
    const void*  img_w       = d_in[4];
    (void)in_sizes; (void)n_in;

    const int prep_blocks = (NPROP + ROWS_PB - 1) / ROWS_PB;   // 63
    prep_kernel<<<prep_blocks, BLK>>>(class_logit, box_reg, proposal,
                                      img_h, img_w);

    // kernel B with programmatic dependent launch: overlap its launch with A
    cudaLaunchConfig_t cfg = {};
    cfg.gridDim  = dim3(GRID, 1, 1);
    cfg.blockDim = dim3(BLK, 1, 1);
    cfg.dynamicSmemBytes = 0;
    cfg.stream = 0;
    cudaLaunchAttribute attr[1];
    attr[0].id = cudaLaunchAttributeProgrammaticStreamSerialization;
    attr[0].val.programmaticStreamSerializationAllowed = 1;
    cfg.attrs = attr;
    cfg.numAttrs = 1;

    float* outp = (float*)d_out;
    cudaLaunchKernelEx(&cfg, roi_main_kernel, outp, out_size);
}

// round 15
// speedup vs baseline: 1.1800x; 1.1800x over previous
#include <cuda_runtime.h>
#include <math.h>

#define NPROP 1000
#define NPAD  1024
#define NCLS  91
#define TOPK  100
#define NMAX  1024
#define MCAP  256           /* fast parallel-NMS path capacity */
#define BLK   256
#define GRID  (NCLS - 1)
#define NITER 4             /* ceil(NPROP / BLK) */
#define SCORE_TH 0.05f
#define NMS_TH   0.5f
#define MIN_SIZE 1.0f
#define BBOX_CLIP 4.1351665567423f   /* log(1000/16) */

// scratch: transposed scores (4B scatter in A, coalesced read in B) + row geometry
__device__ float  g_score[NCLS * NPAD];
__device__ float4 g_prop[NPROP];          // w, h, cx, cy

__device__ __forceinline__ float read_dim(const void* p) {
    int iv = *(const int*)p;
    if (iv >= 1 && iv <= 100000) return (float)iv;        // int32 / int64 low word
    float fv = __int_as_float(iv);
    if (fv >= 1.0f && fv <= 100000.0f) return fv;          // float32
    return (float)iv;
}

// ---- kernel A: warp per row — softmax + transposed score write (4B scatter) ----
__global__ void prep_kernel(const float* __restrict__ class_logit,
                            const float* __restrict__ proposal)
{
    const int gtid = blockIdx.x * blockDim.x + threadIdx.x;
    const int row  = gtid >> 5;
    const int lane = gtid & 31;
    if (row < NPROP) {
        const float* r = class_logit + row * NCLS;
        const float l0 = r[lane];
        const float l1 = r[lane + 32];
        const bool  has2 = (lane + 64 < NCLS);
        const float l2 = has2 ? r[lane + 64] : -3.4e38f;

        float m = fmaxf(l0, fmaxf(l1, l2));
        #pragma unroll
        for (int o = 16; o; o >>= 1) m = fmaxf(m, __shfl_xor_sync(0xffffffffu, m, o));

        const float e0 = expf(l0 - m);
        const float e1 = expf(l1 - m);
        const float e2 = has2 ? expf(l2 - m) : 0.0f;
        float s = e0 + e1 + e2;
        #pragma unroll
        for (int o = 16; o; o >>= 1) s += __shfl_xor_sync(0xffffffffu, s, o);
        const float rinv = 1.0f / s;

        // transposed score writes (skip background class 0)
        if (lane >= 1) g_score[lane * NPAD + row] = e0 * rinv;
        g_score[(lane + 32) * NPAD + row] = e1 * rinv;
        if (has2)      g_score[(lane + 64) * NPAD + row] = e2 * rinv;

        if (lane == 0) {
            const float4 pr = ((const float4*)proposal)[row];
            const float w = pr.z - pr.x;
            const float h = pr.w - pr.y;
            g_prop[row] = make_float4(w, h, pr.x + 0.5f * w, pr.y + 0.5f * h);
        }
    }
    __threadfence();
#if __CUDA_ARCH__ >= 900
    cudaTriggerProgrammaticLaunchCompletion();
#endif
}

// ---- kernel B: coalesced+speculative single-RTT phase 1, decode, sort, NMS ----
__global__ __launch_bounds__(BLK, 1)
void roi_main_kernel(const float* __restrict__ box_reg,       // [N, C*4]
                     const void*  __restrict__ p_img_h,
                     const void*  __restrict__ p_img_w,
                     float* __restrict__ out, int out_size)
{
    const int c    = blockIdx.x + 1;     // foreground class 1..90
    const int tid  = threadIdx.x;
    const int wid  = tid >> 5;
    const int lane = tid & 31;

    __shared__ unsigned long long s_key[NMAX];
    __shared__ float4 s_cbox[NMAX];                 // boxes (compact order)
    __shared__ int    s_perm[NMAX];                 // sorted pos -> compact slot
    __shared__ float4 s_sb[MCAP];                   // boxes in sorted order
    __shared__ unsigned long long s_maskT[MCAP * 4];// transposed suppression matrix
    __shared__ unsigned int s_half[8];              // keep-set, 8x32 bits
    __shared__ unsigned char s_keep[NMAX];          // fallback path only
    __shared__ int    s_list[TOPK];
    __shared__ int    s_mcnt, s_drop, s_cnt;

    const float img_h = read_dim(p_img_h);
    const float img_w = read_dim(p_img_w);

    if (tid == 0) { s_mcnt = 0; s_drop = 0; }
    __syncthreads();

#if __CUDA_ARCH__ >= 900
    cudaGridDependencySynchronize();    // wait for kernel A
#endif

    // ---- phase 1: ALL loads independent -> one memory round-trip ----
    float  sc4[NITER];
    float4 d4[NITER];    // speculative box_reg
    float4 g4[NITER];    // row geometry
    #pragma unroll
    for (int k = 0; k < NITER; ++k) {
        const int p = tid + k * BLK;
        if (p < NPROP) {
            sc4[k] = __ldcg(&g_score[c * NPAD + p]);                       // coalesced
            d4[k]  = __ldg((const float4*)(box_reg + p * (NCLS * 4) + c * 4)); // scattered, indep
            g4[k]  = g_prop[p];                                            // coalesced
        } else {
            sc4[k] = -1.0f;
            d4[k]  = make_float4(0.f, 0.f, 0.f, 0.f);
            g4[k]  = make_float4(0.f, 0.f, 0.f, 0.f);
        }
    }
    #pragma unroll
    for (int k = 0; k < NITER; ++k) {
        const int p = tid + k * BLK;
        if (p < NPROP && sc4[k] >= SCORE_TH) {
            const int slot = atomicAdd(&s_mcnt, 1);

            const float4 g = g4[k];
            const float4 d = d4[k];
            const float dx = d.x * 0.1f;
            const float dy = d.y * 0.1f;
            const float dw = fminf(d.z * 0.2f, BBOX_CLIP);
            const float dh = fminf(d.w * 0.2f, BBOX_CLIP);

            const float pcx = dx * g.x + g.z;
            const float pcy = dy * g.y + g.w;
            const float pw  = expf(dw) * g.x;
            const float ph  = expf(dh) * g.y;

            const float bx1 = fminf(fmaxf(pcx - 0.5f * pw, 0.0f), img_w);
            const float by1 = fminf(fmaxf(pcy - 0.5f * ph, 0.0f), img_h);
            const float bx2 = fminf(fmaxf(pcx + 0.5f * pw, 0.0f), img_w);
            const float by2 = fminf(fmaxf(pcy + 0.5f * ph, 0.0f), img_h);

            s_cbox[slot] = make_float4(bx1, by1, bx2, by2);
            if (bx2 - bx1 < MIN_SIZE || by2 - by1 < MIN_SIZE) {
                // demote: score bits 0, unique low word -> sinks below all valid
                s_key[slot] = (unsigned long long)(unsigned int)(NPROP - p);
                atomicAdd(&s_drop, 1);
            } else {
                s_key[slot] = ((unsigned long long)__float_as_uint(sc4[k]) << 32)
                            | (unsigned int)(NPROP - p);
            }
        }
    }
    __syncthreads();

    const int M    = s_mcnt;
    const int Meff = M - s_drop;     // valid entries occupy sorted pos [0, Meff)

    // ---- rank sort (keys unique -> ranks are a bijection) ----
    for (int i = tid; i < M; i += BLK) {
        const unsigned long long ki = s_key[i];
        int r = 0;
        for (int j = 0; j < M; ++j) r += (s_key[j] > ki);
        s_perm[r] = i;
    }
    __syncthreads();

    const bool fast = (Meff <= MCAP);

    if (fast) {
        // ---- materialize sorted boxes; init keep-set over [0, Meff) ----
        for (int i = tid; i < Meff; i += BLK) s_sb[i] = s_cbox[s_perm[i]];
        if (tid < 8) {
            const int lo = tid * 32;
            s_half[tid] = (Meff >= lo + 32) ? 0xffffffffu
                        : (Meff <= lo) ? 0u
                        : ((1u << (Meff - lo)) - 1u);
        }
        __syncthreads();

        // ---- transposed suppression matrix: bit j of row i iff j<i & IoU>th ----
        for (int t = tid; t < Meff * 4; t += BLK) {
            const int i = t >> 2;
            const int w = t & 3;
            unsigned long long bits = 0ULL;
            const int jbase = w << 6;
            const int jend  = min(jbase + 64, i);     // j < i only
            if (jend > jbase) {
                const float4 a = s_sb[i];
                const float area_a = (a.z - a.x) * (a.w - a.y);
                for (int j = jbase; j < jend; ++j) {
                    const float4 b = s_sb[j];
                    const float area_b = (b.z - b.x) * (b.w - b.y);
                    const float iw = fmaxf(fminf(a.z, b.z) - fmaxf(a.x, b.x), 0.0f);
                    const float ih = fmaxf(fminf(a.w, b.w) - fmaxf(a.y, b.y), 0.0f);
                    const float inter = iw * ih;
                    const float uni   = fmaxf(area_a + area_b - inter, 1e-6f);
                    if (inter > NMS_TH * uni) bits |= 1ULL << (j - jbase);
                }
            }
            s_maskT[t] = bits;
        }
        __syncthreads();

        // ---- parallel Jacobi fixpoint == greedy NMS (unique fixpoint) ----
        const int i = tid;
        int guard = 0;
        for (;;) {
            bool nk = false, ch = false;
            if (i < Meff) {
                const unsigned long long k0 =
                    (unsigned long long)s_half[0] | ((unsigned long long)s_half[1] << 32);
                const unsigned long long k1 =
                    (unsigned long long)s_half[2] | ((unsigned long long)s_half[3] << 32);
                const unsigned long long k2 =
                    (unsigned long long)s_half[4] | ((unsigned long long)s_half[5] << 32);
                const unsigned long long k3 =
                    (unsigned long long)s_half[6] | ((unsigned long long)s_half[7] << 32);
                const unsigned long long sup =
                      (s_maskT[i * 4 + 0] & k0) | (s_maskT[i * 4 + 1] & k1)
                    | (s_maskT[i * 4 + 2] & k2) | (s_maskT[i * 4 + 3] & k3);
                nk = (sup == 0ULL);
                const bool cur = (s_half[i >> 5] >> (i & 31)) & 1u;
                ch = (nk != cur);
            }
            const unsigned int bal = __ballot_sync(0xffffffffu, nk);
            __syncthreads();                      // all reads done before rewrite
            if (lane == 0) s_half[wid] = bal;     // 8 warps cover 8 words exactly
            if (!__syncthreads_or((int)ch)) break;
            if (++guard > MCAP) break;            // safety bound (never hit)
        }

        // ---- top-K compaction from 8 keep words (register-only ffs loop) ----
        if (tid == 0) {
            int cnt = 0;
            #pragma unroll
            for (int hw = 0; hw < 8; ++hw) {
                unsigned int a = s_half[hw];
                while (a && cnt < TOPK) {
                    const int b = __ffs(a) - 1;
                    s_list[cnt++] = hw * 32 + b;
                    a &= a - 1;
                }
            }
            s_cnt = cnt;
        }
        __syncthreads();
    } else {
        // ---- fallback: barrier-per-round NMS over sorted order (any M) ----
        for (int i = tid; i < Meff; i += BLK) s_keep[i] = 1;
        __syncthreads();
        for (int i = 0; i < Meff - 1; ++i) {
            if (!s_keep[i]) continue;
            const float4 a = s_cbox[s_perm[i]];
            const float area_a = (a.z - a.x) * (a.w - a.y);
            for (int j = i + 1 + tid; j < Meff; j += BLK) {
                if (!s_keep[j]) continue;
                const float4 b = s_cbox[s_perm[j]];
                const float area_b = (b.z - b.x) * (b.w - b.y);
                const float iw = fmaxf(fminf(a.z, b.z) - fmaxf(a.x, b.x), 0.0f);
                const float ih = fmaxf(fminf(a.w, b.w) - fmaxf(a.y, b.y), 0.0f);
                const float inter = iw * ih;
                const float uni   = fmaxf(area_a + area_b - inter, 1e-6f);
                if (inter > NMS_TH * uni) s_keep[j] = 0;
            }
            __syncthreads();
        }
        if (tid == 0) {
            int cnt = 0;
            for (int i = 0; i < Meff && cnt < TOPK; ++i)
                if (s_keep[i]) s_list[cnt++] = i;
            s_cnt = cnt;
        }
        __syncthreads();
    }

    // ---- write output: dets [9000,5] then labels [9000] (as float) ----
    if (tid < TOPK) {
        const int r = (c - 1) * TOPK + tid;
        float b0 = 0.f, b1 = 0.f, b2 = 0.f, b3 = 0.f, sc = 0.f, lab = 0.f;
        if (tid < s_cnt) {
            const int pos  = s_list[tid];
            const int slot = s_perm[pos];
            const float4 b = fast ? s_sb[pos] : s_cbox[slot];
            b0 = b.x; b1 = b.y; b2 = b.z; b3 = b.w;
            sc = __uint_as_float((unsigned int)(s_key[slot] >> 32));
            lab = (float)c;
        }
        out[r * 5 + 0] = b0;
        out[r * 5 + 1] = b1;
        out[r * 5 + 2] = b2;
        out[r * 5 + 3] = b3;
        out[r * 5 + 4] = sc;
        const int dets_elems = (NCLS - 1) * TOPK * 5;        // 45000
        if (out_size >= dets_elems + (NCLS - 1) * TOPK)
            out[dets_elems + r] = lab;
    }
}

extern "C" void kernel_launch(void* const* d_in, const int* in_sizes, int n_in,
                              void* d_out, int out_size)
{
    const float* class_logit = (const float*)d_in[0];
    const float* box_reg     = (const float*)d_in[1];
    const float* proposal    = (const float*)d_in[2];
    const void*  img_h       = d_in[3];
    const void*  img_w       = d_in[4];
    (void)in_sizes; (void)n_in;

    prep_kernel<<<(NPROP * 32 + 255) / 256, 256>>>(class_logit, proposal);

    // kernel B with programmatic dependent launch: overlap its launch with A
    cudaLaunchConfig_t cfg = {};
    cfg.gridDim  = dim3(GRID, 1, 1);
    cfg.blockDim = dim3(BLK, 1, 1);
    cfg.dynamicSmemBytes = 0;
    cfg.stream = 0;
    cudaLaunchAttribute attr[1];
    attr[0].id = cudaLaunchAttributeProgrammaticStreamSerialization;
    attr[0].val.programmaticStreamSerializationAllowed = 1;
    cfg.attrs = attr;
    cfg.numAttrs = 1;

    float* outp = (float*)d_out;
    cudaLaunchKernelEx(&cfg, roi_main_kernel,
                       box_reg, (const void*)img_h, (const void*)img_w,
                       outp, out_size);
}